// round 2
// baseline (speedup 1.0000x reference)
#include <cuda_runtime.h>
#include <cuda_bf16.h>

// Problem: NGFTextureFetch — bilinear sampling of per-complex feature maps.
// map: [2048, 16, 16, 64] f32   (64 KB per complex)
// u,v: [2048, 256] f32          (sample coords in [0,1])
// out: [2048, 256, 64] f32
//
// Strategy: 1 CTA per complex. Stage the 64KB map in SMEM (coalesced float4),
// then 16 threads per sample each produce one float4 of the 64-feature output.
// Output stores are fully coalesced (512B contiguous per warp).

#define NC   2048
#define RH   16
#define RW   16
#define NF   64
#define NP   256
#define F4   (NF / 4)          // 16 float4 per texel
#define TPB  256

__global__ __launch_bounds__(TPB, 3)
void ngf_bilerp_kernel(const float* __restrict__ map,
                       const float* __restrict__ u,
                       const float* __restrict__ v,
                       float* __restrict__ out)
{
    extern __shared__ float4 smap[];   // [RH*RW*F4] = 4096 float4 = 64 KB

    const int c   = blockIdx.x;
    const int tid = threadIdx.x;

    // ---- Stage map[c] into SMEM: 4096 float4, 16 per thread, coalesced ----
    const float4* gmap = reinterpret_cast<const float4*>(map + (size_t)c * (RH * RW * NF));
#pragma unroll
    for (int i = 0; i < 16; ++i) {
        smap[i * TPB + tid] = gmap[i * TPB + tid];
    }

    // ---- Stage u,v (256 floats each) to SMEM to avoid redundant gmem reads ----
    __shared__ float su[NP];
    __shared__ float sv[NP];
    if (tid < NP) {
        su[tid] = u[(size_t)c * NP + tid];
        sv[tid] = v[(size_t)c * NP + tid];
    }
    __syncthreads();

    float4* outc = reinterpret_cast<float4*>(out + (size_t)c * NP * NF);

    // ---- 4096 output float4s per block: 16 threads/sample x 256 samples ----
#pragma unroll
    for (int i = 0; i < 16; ++i) {
        const int task = i * TPB + tid;
        const int p  = task >> 4;     // sample index (0..255)
        const int f4 = task & 15;     // float4 lane within 64 feats

        const float x = su[p] * (float)(RW - 1);
        const float y = sv[p] * (float)(RH - 1);
        int x0 = (int)floorf(x);
        int y0 = (int)floorf(y);
        x0 = min(max(x0, 0), RW - 2);
        y0 = min(max(y0, 0), RH - 2);
        const float fx = x - (float)x0;
        const float fy = y - (float)y0;
        const float wx0 = 1.0f - fx, wx1 = fx;
        const float wy0 = 1.0f - fy, wy1 = fy;

        const float4* g = smap + (y0 * RW + x0) * F4 + f4;
        const float4 a = g[0];            // (y0,   x0)
        const float4 b = g[F4];           // (y0,   x0+1)
        const float4 cc = g[RW * F4];     // (y0+1, x0)
        const float4 d = g[(RW + 1) * F4];// (y0+1, x0+1)

        float4 r;
        r.x = (a.x * wx0 + b.x * wx1) * wy0 + (cc.x * wx0 + d.x * wx1) * wy1;
        r.y = (a.y * wx0 + b.y * wx1) * wy0 + (cc.y * wx0 + d.y * wx1) * wy1;
        r.z = (a.z * wx0 + b.z * wx1) * wy0 + (cc.z * wx0 + d.z * wx1) * wy1;
        r.w = (a.w * wx0 + b.w * wx1) * wy0 + (cc.w * wx0 + d.w * wx1) * wy1;

        outc[task] = r;
    }
}

extern "C" void kernel_launch(void* const* d_in, const int* in_sizes, int n_in,
                              void* d_out, int out_size)
{
    const float* map = (const float*)d_in[0];
    const float* u   = (const float*)d_in[1];
    const float* v   = (const float*)d_in[2];
    float* out       = (float*)d_out;

    const int smem_bytes = RH * RW * F4 * (int)sizeof(float4);  // 65536
    cudaFuncSetAttribute(ngf_bilerp_kernel,
                         cudaFuncAttributeMaxDynamicSharedMemorySize, smem_bytes);

    ngf_bilerp_kernel<<<NC, TPB, smem_bytes>>>(map, u, v, out);
}

// round 4
// speedup vs baseline: 1.1153x; 1.1153x over previous
#include <cuda_runtime.h>
#include <cuda_bf16.h>
#include <cstdint>

// NGFTextureFetch — bilinear sampling of per-complex feature maps.
// map: [2048, 16, 16, 64] f32 (64 KB/complex), u,v: [2048, 256] f32
// out: [2048, 256, 64] f32
//
// Persistent-CTA, double-buffered TMA (cp.async.bulk) pipeline:
//   - 148 CTAs x 512 threads, one CTA per SM, each handles ~14 complexes.
//   - Two smem buffers (map+u+v = 67584 B each). While warps bilerp+store
//     complex k from buf[k&1], thread 0 has already launched the bulk async
//     copy of complex k+1 (and launches k+2 after the buffer frees).
//   - DRAM read stream (TMA) and write stream (STG.128) run concurrently.

#define NC   2048
#define RH   16
#define RW   16
#define NF   64
#define NP   256
#define TPB  512
#define GRID 148

#define MAP_BYTES (RH * RW * NF * 4)          // 65536
#define UV_BYTES  (NP * 4)                    // 1024
#define BUF_BYTES (MAP_BYTES + 2 * UV_BYTES)  // 67584
#define SMEM_DYN  (2 * BUF_BYTES)             // 135168

__device__ __forceinline__ uint32_t smem_u32(const void* p) {
    return (uint32_t)__cvta_generic_to_shared(p);
}

__device__ __forceinline__ void bulk_copy_g2s(uint32_t dst, const void* src,
                                              uint32_t bytes, uint32_t mbar) {
    asm volatile(
        "cp.async.bulk.shared::cta.global.mbarrier::complete_tx::bytes "
        "[%0], [%1], %2, [%3];"
        :: "r"(dst), "l"(src), "r"(bytes), "r"(mbar) : "memory");
}

__device__ __forceinline__ void mbar_wait(uint32_t mbar, uint32_t parity) {
    uint32_t done;
    do {
        asm volatile(
            "{\n\t.reg .pred p;\n\t"
            "mbarrier.try_wait.parity.shared.b64 p, [%1], %2;\n\t"
            "selp.b32 %0, 1, 0, p;\n\t}"
            : "=r"(done) : "r"(mbar), "r"(parity) : "memory");
    } while (!done);
}

__global__ __launch_bounds__(TPB, 1)
void ngf_persistent_kernel(const float* __restrict__ map,
                           const float* __restrict__ u,
                           const float* __restrict__ v,
                           float* __restrict__ out)
{
    extern __shared__ __align__(128) unsigned char smem[];
    __shared__ __align__(8) uint64_t mbar_s[2];

    const int tid = threadIdx.x;
    const int cta = blockIdx.x;

    const uint32_t mb0 = smem_u32(&mbar_s[0]);
    const uint32_t mb1 = smem_u32(&mbar_s[1]);

    if (tid == 0) {
        asm volatile("mbarrier.init.shared.b64 [%0], 1;" :: "r"(mb0));
        asm volatile("mbarrier.init.shared.b64 [%0], 1;" :: "r"(mb1));
        asm volatile("fence.proxy.async.shared::cta;" ::: "memory");
    }
    __syncthreads();

    // complexes: c = cta + k * GRID, k in [0, n_my)
    const int n_my = (NC - cta + GRID - 1) / GRID;

    // issue staging of complex (cta + k*GRID) into buffer slot
    auto issue = [&](int k, int slot) {
        const int c = cta + k * GRID;
        const uint32_t mb  = slot ? mb1 : mb0;
        const uint32_t dst = smem_u32(smem) + slot * BUF_BYTES;
        asm volatile(
            "mbarrier.arrive.expect_tx.shared.b64 _, [%0], %1;"
            :: "r"(mb), "r"((uint32_t)BUF_BYTES) : "memory");
        const char* gm = (const char*)(map + (size_t)c * (RH * RW * NF));
        #pragma unroll
        for (int q = 0; q < 4; ++q)
            bulk_copy_g2s(dst + q * 16384, gm + q * 16384, 16384, mb);
        bulk_copy_g2s(dst + MAP_BYTES,            u + (size_t)c * NP, UV_BYTES, mb);
        bulk_copy_g2s(dst + MAP_BYTES + UV_BYTES, v + (size_t)c * NP, UV_BYTES, mb);
    };

    if (tid == 0) {
        issue(0, 0);
        if (n_my > 1) issue(1, 1);
    }

    for (int k = 0; k < n_my; ++k) {
        const int slot = k & 1;
        const uint32_t parity = (k >> 1) & 1;
        mbar_wait(slot ? mb1 : mb0, parity);

        const float4* smap = (const float4*)(smem + slot * BUF_BYTES);
        const float*  su   = (const float*)(smem + slot * BUF_BYTES + MAP_BYTES);
        const float*  sv   = su + NP;

        const int c = cta + k * GRID;
        float4* outc = (float4*)(out + (size_t)c * (NP * NF));

        #pragma unroll 4
        for (int i = 0; i < 8; ++i) {
            const int task = i * TPB + tid;     // 0..4095
            const int p    = task >> 4;         // sample
            const int f4i  = task & 15;         // float4 lane within 64 feats

            const float x = su[p] * (float)(RW - 1);
            const float y = sv[p] * (float)(RH - 1);
            int x0 = (int)floorf(x);
            int y0 = (int)floorf(y);
            x0 = min(max(x0, 0), RW - 2);
            y0 = min(max(y0, 0), RH - 2);
            const float fx = x - (float)x0;
            const float fy = y - (float)y0;
            const float wx0 = 1.0f - fx, wx1 = fx;
            const float wy0 = 1.0f - fy, wy1 = fy;

            const float4* g = smap + ((y0 * RW + x0) << 4) + f4i;
            const float4 a  = g[0];                 // (y0,   x0)
            const float4 b  = g[16];                // (y0,   x0+1)
            const float4 cc = g[RW * 16];           // (y0+1, x0)
            const float4 d  = g[(RW + 1) * 16];     // (y0+1, x0+1)

            float4 r;
            r.x = (a.x * wx0 + b.x * wx1) * wy0 + (cc.x * wx0 + d.x * wx1) * wy1;
            r.y = (a.y * wx0 + b.y * wx1) * wy0 + (cc.y * wx0 + d.y * wx1) * wy1;
            r.z = (a.z * wx0 + b.z * wx1) * wy0 + (cc.z * wx0 + d.z * wx1) * wy1;
            r.w = (a.w * wx0 + b.w * wx1) * wy0 + (cc.w * wx0 + d.w * wx1) * wy1;

            outc[task] = r;
        }

        __syncthreads();                    // all reads of buf[slot] done
        if (tid == 0 && k + 2 < n_my)
            issue(k + 2, slot);             // refill the freed buffer
    }
}

extern "C" void kernel_launch(void* const* d_in, const int* in_sizes, int n_in,
                              void* d_out, int out_size)
{
    const float* map = (const float*)d_in[0];
    const float* u   = (const float*)d_in[1];
    const float* v   = (const float*)d_in[2];
    float* out       = (float*)d_out;

    cudaFuncSetAttribute(ngf_persistent_kernel,
                         cudaFuncAttributeMaxDynamicSharedMemorySize, SMEM_DYN);

    ngf_persistent_kernel<<<GRID, TPB, SMEM_DYN>>>(map, u, v, out);
}